// round 15
// baseline (speedup 1.0000x reference)
#include <cuda_runtime.h>
#include <cuda_bf16.h>
#include <cuda_fp16.h>
#include <cstdint>

// Problem constants (GCN_60301340836134)
constexpr int N_NODES = 100000;
constexpr int N_EDGES = 1600000;
constexpr int D_IN    = 128;
constexpr int D_OUT   = 5;
constexpr int NOUT2   = 2 * D_OUT;          // 10 fused outputs (W_l | W_r)
constexpr int AGG_PAD = 8;                  // f32 rows: [y0..y4, deg, pad, pad]
constexpr int YL_PADH = 8;                  // fp16 rows: 16B = one LDG.128

constexpr int K4      = D_IN / 4;           // 32 float4 per x row
constexpr int WPAD    = 11;                 // sW row stride (float4)

// proj pipeline geometry
constexpr int CH      = 64;                 // nodes per chunk
constexpr int NCH     = 4;                  // chunks per CTA
constexpr int NODES_PER_CTA = CH * NCH;     // 256
constexpr int XR      = 33;                 // smem x row stride (float4), padded
constexpr int SX_F4   = CH * XR;            // 2112 float4 per stage
// dynamic smem layout (in float4 units): [sx0][sx1][sW][sb]
constexpr int OFF_SX0 = 0;
constexpr int OFF_SX1 = SX_F4;
constexpr int OFF_SW  = 2 * SX_F4;
constexpr int OFF_SB  = OFF_SW + K4 * WPAD;           // bias: 2 float4
constexpr int SMEM_F4 = OFF_SB + 2;
constexpr int SMEM_BYTES = SMEM_F4 * 16;              // ~73.3 KB

// Scratch (no allocations allowed; device globals)
__device__ __align__(16) __half g_ylh [N_NODES * YL_PADH];  // x@W_l^T (fp16)
__device__ __align__(16) float  g_agg [N_NODES * AGG_PAD];  // sums + deg
__device__ __align__(16) float  g_base[N_NODES * AGG_PAD];  // x@W_r^T + b_l

// ---------------------------------------------------------------------------
// PTX helpers
// ---------------------------------------------------------------------------
__device__ __forceinline__ void red_add_v4(float* addr, float4 v) {
    asm volatile("red.global.add.v4.f32 [%0], {%1, %2, %3, %4};"
                 :: "l"(addr), "f"(v.x), "f"(v.y), "f"(v.z), "f"(v.w)
                 : "memory");
}
__device__ __forceinline__ void red_add_v2(float* addr, float a, float b) {
    asm volatile("red.global.add.v2.f32 [%0], {%1, %2};"
                 :: "l"(addr), "f"(a), "f"(b)
                 : "memory");
}
__device__ __forceinline__ void cp_async16(uint32_t saddr, const void* gptr) {
    asm volatile("cp.async.cg.shared.global [%0], [%1], 16;"
                 :: "r"(saddr), "l"(gptr) : "memory");
}
__device__ __forceinline__ void cp_commit() {
    asm volatile("cp.async.commit_group;" ::: "memory");
}
template <int N>
__device__ __forceinline__ void cp_wait() {
    asm volatile("cp.async.wait_group %0;" :: "n"(N) : "memory");
}

// ---------------------------------------------------------------------------
// proj chunk copy: stage CH=64 node rows into smem via cp.async (8 per thread)
// ---------------------------------------------------------------------------
__device__ __forceinline__ void stage_chunk(
    const float4* __restrict__ x4, float4* sx, uint32_t sx_u32,
    int chunk_node_base, int tid)
{
#pragma unroll
    for (int j = 0; j < 8; j++) {
        int idx = j * 256 + tid;        // 0..2047
        int ln  = idx >> 5;             // local node 0..63
        int k   = idx & 31;             // float4 chunk 0..31
        int gn  = chunk_node_base + ln;
        if (gn >= N_NODES) gn = 0;      // clamp: safe read, store guarded later
        const void* src = (const void*)(x4 + (size_t)gn * K4 + k);
        uint32_t dst = sx_u32 + (uint32_t)((ln * XR + k) * 16);
        cp_async16(dst, src);
    }
    cp_commit();
}

// ---------------------------------------------------------------------------
// proj chunk compute: 8 lanes per node, 2 nodes per thread, x from smem
// ---------------------------------------------------------------------------
__device__ __forceinline__ void compute_chunk(
    const float4* sx, const float4* sW, const float* sb,
    int chunk_node_base, int tid)
{
    const int g = tid >> 3;             // group 0..31
    const int c = tid & 7;              // chunk-in-tile 0..7

    float acc[2][NOUT2];
#pragma unroll
    for (int j = 0; j < 2; j++)
#pragma unroll
        for (int o = 0; o < NOUT2; o++) acc[j][o] = 0.f;

#pragma unroll
    for (int t = 0; t < 4; t++) {
        const int k4i = t * 8 + c;
        float4 xv0 = sx[(g * 2 + 0) * XR + k4i];
        float4 xv1 = sx[(g * 2 + 1) * XR + k4i];
#pragma unroll
        for (int o = 0; o < NOUT2; o++) {
            float4 w = sW[k4i * WPAD + o];
            acc[0][o] += xv0.x * w.x + xv0.y * w.y + xv0.z * w.z + xv0.w * w.w;
            acc[1][o] += xv1.x * w.x + xv1.y * w.y + xv1.z * w.z + xv1.w * w.w;
        }
    }

#pragma unroll
    for (int j = 0; j < 2; j++)
#pragma unroll
        for (int o = 0; o < NOUT2; o++) {
            acc[j][o] += __shfl_xor_sync(0xFFFFFFFFu, acc[j][o], 4);
            acc[j][o] += __shfl_xor_sync(0xFFFFFFFFu, acc[j][o], 2);
            acc[j][o] += __shfl_xor_sync(0xFFFFFFFFu, acc[j][o], 1);
        }

    if (c == 0) {
#pragma unroll
        for (int j = 0; j < 2; j++) {
            int node = chunk_node_base + g * 2 + j;
            if (node >= N_NODES) continue;

            __half2 h01 = __floats2half2_rn(acc[j][0], acc[j][1]);
            __half2 h23 = __floats2half2_rn(acc[j][2], acc[j][3]);
            __half2 h4z = __floats2half2_rn(acc[j][4], 0.f);
            uint4 u;
            u.x = *(unsigned*)&h01;
            u.y = *(unsigned*)&h23;
            u.z = *(unsigned*)&h4z;
            u.w = 0u;
            ((uint4*)(g_ylh + (size_t)node * YL_PADH))[0] = u;

            float4* bp = (float4*)(g_base + (size_t)node * AGG_PAD);
            bp[0] = make_float4(acc[j][5] + sb[0], acc[j][6] + sb[1],
                                acc[j][7] + sb[2], acc[j][8] + sb[3]);
            bp[1] = make_float4(acc[j][9] + sb[4], 0.f, 0.f, 0.f);
        }
    }
}

// ---------------------------------------------------------------------------
// Kernel 1: projection, cp.async double-buffered. 256 nodes per CTA.
// Also zeroes g_agg (512 float4 per block).
// ---------------------------------------------------------------------------
__global__ __launch_bounds__(256, 3) void proj_kernel(
    const float* __restrict__ x,
    const float* __restrict__ Wl,
    const float* __restrict__ bl,
    const float* __restrict__ Wr)
{
    extern __shared__ float4 smem[];
    float4* sx0 = smem + OFF_SX0;
    float4* sx1 = smem + OFF_SX1;
    float4* sW  = smem + OFF_SW;
    float*  sb  = (float*)(smem + OFF_SB);

    const int tid  = threadIdx.x;
    const int base = blockIdx.x * NODES_PER_CTA;

    uint32_t sx0_u32 = (uint32_t)__cvta_generic_to_shared(sx0);
    uint32_t sx1_u32 = (uint32_t)__cvta_generic_to_shared(sx1);

    // prolog: prefetch chunk 0
    const float4* x4 = (const float4*)x;
    stage_chunk(x4, sx0, sx0_u32, base, tid);

    // zero g_agg: 200000 float4 over 391 blocks * 512
    {
        constexpr int AGG_F4 = (N_NODES * AGG_PAD) / 4;  // 200000
#pragma unroll
        for (int k = 0; k < 2; k++) {
            int zi = blockIdx.x * 512 + k * 256 + tid;
            if (zi < AGG_F4)
                ((float4*)g_agg)[zi] = make_float4(0.f, 0.f, 0.f, 0.f);
        }
    }

    // stage weights + bias (strided: 320 entries > 256 threads)
    for (int i = tid; i < K4 * NOUT2; i += 256) {
        int k4 = i / NOUT2;
        int o  = i - k4 * NOUT2;
        sW[k4 * WPAD + o] = (o < D_OUT)
            ? ((const float4*)Wl)[o * K4 + k4]
            : ((const float4*)Wr)[(o - D_OUT) * K4 + k4];
    }
    if (tid < D_OUT) sb[tid] = bl[tid];

    // chunk 0: prefetch 1, wait 0, compute 0
    stage_chunk(x4, sx1, sx1_u32, base + CH, tid);
    cp_wait<1>();
    __syncthreads();                 // covers weights + chunk0 data
    compute_chunk(sx0, sW, sb, base, tid);
    __syncthreads();

    // chunk 1: prefetch 2 -> buf0, wait, compute buf1
    stage_chunk(x4, sx0, sx0_u32, base + 2 * CH, tid);
    cp_wait<1>();
    __syncthreads();
    compute_chunk(sx1, sW, sb, base + CH, tid);
    __syncthreads();

    // chunk 2: prefetch 3 -> buf1, wait, compute buf0
    stage_chunk(x4, sx1, sx1_u32, base + 3 * CH, tid);
    cp_wait<1>();
    __syncthreads();
    compute_chunk(sx0, sW, sb, base + 2 * CH, tid);
    __syncthreads();

    // chunk 3: wait all, compute buf1
    cp_wait<0>();
    __syncthreads();
    compute_chunk(sx1, sW, sb, base + 3 * CH, tid);
}

// ---------------------------------------------------------------------------
// Kernel 2: edge scatter. 4 edges per thread (int4 index loads).
// Per edge: ONE 16B gather (8 fp16) + v4.f32 RED + v2.f32 RED.
// ---------------------------------------------------------------------------
__global__ __launch_bounds__(256) void scatter_kernel(
    const int* __restrict__ src,
    const int* __restrict__ dst)
{
    constexpr int E4 = N_EDGES / 4;  // 400000
    int t = blockIdx.x * blockDim.x + threadIdx.x;
    if (t >= E4) return;

    int4 s4 = ((const int4*)src)[t];
    int4 d4 = ((const int4*)dst)[t];

    int ss[4] = {s4.x, s4.y, s4.z, s4.w};
    int dd[4] = {d4.x, d4.y, d4.z, d4.w};

    uint4 u[4];
#pragma unroll
    for (int k = 0; k < 4; k++) {
        unsigned s = (unsigned)ss[k];
        if (s >= (unsigned)N_NODES) s = 0;  // defensive
        u[k] = ((const uint4*)(g_ylh + (size_t)s * YL_PADH))[0];
    }

#pragma unroll
    for (int k = 0; k < 4; k++) {
        unsigned d = (unsigned)dd[k];
        if (d >= (unsigned)N_NODES) continue;

        __half2 h01 = *(__half2*)&u[k].x;
        __half2 h23 = *(__half2*)&u[k].y;
        __half2 h4z = *(__half2*)&u[k].z;
        float2 f01 = __half22float2(h01);
        float2 f23 = __half22float2(h23);
        float  f4  = __low2float(h4z);

        float* ag = g_agg + (size_t)d * AGG_PAD;
        red_add_v4(ag, make_float4(f01.x, f01.y, f23.x, f23.y));
        red_add_v2(ag + 4, f4, 1.0f);
    }
}

// ---------------------------------------------------------------------------
// Kernel 3: finalize, fully coalesced.
//   out[n][o] = base[n][o] + agg[n][o] / max(deg, 1)
// ---------------------------------------------------------------------------
__global__ __launch_bounds__(256) void finalize_kernel(float* __restrict__ out)
{
    __shared__ float s_out[256 * D_OUT];  // 1280 floats = 320 float4

    int tid  = threadIdx.x;
    int node = blockIdx.x * 256 + tid;

    if (node < N_NODES) {
        const float4* ap = (const float4*)(g_agg  + (size_t)node * AGG_PAD);
        const float4* bp = (const float4*)(g_base + (size_t)node * AGG_PAD);
        float4 a0 = ap[0], a1 = ap[1];
        float4 b0 = bp[0], b1 = bp[1];

        float inv = 1.0f / fmaxf(a1.y, 1.0f);   // deg in lane 5

        s_out[tid * D_OUT + 0] = b0.x + a0.x * inv;
        s_out[tid * D_OUT + 1] = b0.y + a0.y * inv;
        s_out[tid * D_OUT + 2] = b0.z + a0.z * inv;
        s_out[tid * D_OUT + 3] = b0.w + a0.w * inv;
        s_out[tid * D_OUT + 4] = b1.x + a1.x * inv;
    }
    __syncthreads();

    int base_f  = blockIdx.x * 256 * D_OUT;
    int total_f = N_NODES * D_OUT;
#pragma unroll
    for (int j = tid; j < 320; j += 256) {
        int f = base_f + j * 4;
        if (f + 3 < total_f) {
            ((float4*)out)[base_f / 4 + j] = ((const float4*)s_out)[j];
        } else if (f < total_f) {
            for (int q = 0; q < total_f - f; q++)
                out[f + q] = s_out[j * 4 + q];
        }
    }
}

// ---------------------------------------------------------------------------
// Launch
// Inputs (metadata order): x [N*128 f32], edge_index [2*E int32 on device],
//                          W_l [5*128 f32], b_l [5 f32], W_r [5*128 f32]
// Output: [N*5 f32]
// ---------------------------------------------------------------------------
extern "C" void kernel_launch(void* const* d_in, const int* in_sizes, int n_in,
                              void* d_out, int out_size)
{
    const float* x    = (const float*)d_in[0];
    const int*   eidx = (const int*)d_in[1];
    const float* Wl   = (const float*)d_in[2];
    const float* bl   = (const float*)d_in[3];
    const float* Wr   = (const float*)d_in[4];
    float*       out  = (float*)d_out;

    const int* src = eidx;            // edge_index[0]
    const int* dst = eidx + N_EDGES;  // edge_index[1]

    {
        // idempotent, stateless, not a stream op (graph-capture safe);
        // called every time per harness "no static guards" rule
        cudaFuncSetAttribute(proj_kernel,
                             cudaFuncAttributeMaxDynamicSharedMemorySize,
                             SMEM_BYTES);
        int blocks = (N_NODES + NODES_PER_CTA - 1) / NODES_PER_CTA;  // 391
        proj_kernel<<<blocks, 256, SMEM_BYTES>>>(x, Wl, bl, Wr);
    }
    {
        constexpr int E4 = N_EDGES / 4;
        scatter_kernel<<<(E4 + 255) / 256, 256>>>(src, dst);
    }
    {
        int blocks = (N_NODES + 255) / 256;
        finalize_kernel<<<blocks, 256>>>(out);
    }
}

// round 16
// speedup vs baseline: 1.4375x; 1.4375x over previous
#include <cuda_runtime.h>
#include <cuda_bf16.h>
#include <cuda_fp16.h>
#include <cstdint>

// Problem constants (GCN_60301340836134)
constexpr int N_NODES = 100000;
constexpr int N_EDGES = 1600000;
constexpr int D_IN    = 128;
constexpr int D_OUT   = 5;
constexpr int NOUT2   = 2 * D_OUT;          // 10 fused outputs (W_l | W_r)
constexpr int AGG_PAD = 8;                  // base rows: [b0..b4,pad..] f32
constexpr int YL_PADH = 8;                  // fp16 rows: 16B = one LDG.128

constexpr int K4      = D_IN / 4;           // 32 float4 per x row
constexpr int WPAD    = 11;                 // sW row stride (float4)
constexpr int NPT     = 4;                  // nodes per thread (R12 config)
constexpr int NPB2    = 128;                // nodes per block (32 groups * 4)

// Scratch (no allocations allowed; device globals)
__device__ __align__(16) __half g_ylh [N_NODES * YL_PADH];  // x@W_l^T (fp16)
__device__ __align__(16) __half g_aggh[N_NODES * YL_PADH];  // fp16 sums+cnt
__device__ __align__(16) float  g_base[N_NODES * AGG_PAD];  // x@W_r^T + b_l

// ---------------------------------------------------------------------------
// Packed-half vector reduction (sm_90+): 8 fp16 adds in ONE L2 op
// ---------------------------------------------------------------------------
__device__ __forceinline__ void red_add_v4_f16x2(__half* addr, uint4 v) {
    asm volatile("red.global.add.noftz.v4.f16x2 [%0], {%1, %2, %3, %4};"
                 :: "l"(addr), "r"(v.x), "r"(v.y), "r"(v.z), "r"(v.w)
                 : "memory");
}

// ---------------------------------------------------------------------------
// Kernel 1: projection (exact R12 structure: 8 lanes/node-group, 4 nodes per
// thread, ALL 16 LDG.128 up front, 2 CTA/SM). Also zeroes g_aggh.
//   g_ylh[node]  = fp16(x[node] @ W_l^T), slots 5..7 = 0
//   g_base[node] = x[node] @ W_r^T + b_l
// ---------------------------------------------------------------------------
__global__ __launch_bounds__(256, 2) void proj_kernel(
    const float* __restrict__ x,
    const float* __restrict__ Wl,
    const float* __restrict__ bl,
    const float* __restrict__ Wr)
{
    __shared__ float4 sW[K4 * WPAD];   // [k4][o], stride 11
    __shared__ float  sb[D_OUT];

    const int tid   = threadIdx.x;
    const int g     = tid >> 3;        // group in block (0..31)
    const int c     = tid & 7;         // float4-chunk within tile (0..7)
    const int nbase = blockIdx.x * NPB2 + g * NPT;

    // zero g_aggh: 100000 uint4 rows over 782 blocks * 128
    {
        if (tid < 128) {
            int zi = blockIdx.x * 128 + tid;
            if (zi < N_NODES)
                ((uint4*)g_aggh)[zi] = make_uint4(0u, 0u, 0u, 0u);
        }
    }

    // stage weights (strided loop: 320 entries > 256 threads)
    for (int i = tid; i < K4 * NOUT2; i += 256) {
        int k4 = i / NOUT2;
        int o  = i - k4 * NOUT2;
        sW[k4 * WPAD + o] = (o < D_OUT)
            ? ((const float4*)Wl)[o * K4 + k4]
            : ((const float4*)Wr)[(o - D_OUT) * K4 + k4];
    }
    if (tid < D_OUT) sb[tid] = bl[tid];

    const float4* x4 = (const float4*)x;

    // ---- phase 1: issue ALL 16 coalesced LDG.128 back-to-back ----
    float4 xv[NPT][4];
#pragma unroll
    for (int j = 0; j < NPT; j++) {
        int node = nbase + j;
        int nc   = (node < N_NODES) ? node : 0;   // clamp (tail block)
        const float4* row = x4 + (size_t)nc * K4 + c;
#pragma unroll
        for (int t = 0; t < 4; t++)
            xv[j][t] = row[t * 8];
    }

    __syncthreads();   // weights visible (overlaps with LDGs in flight)

    // ---- phase 2: compute, weights streamed from smem per tile ----
    float acc[NPT][NOUT2];
#pragma unroll
    for (int j = 0; j < NPT; j++)
#pragma unroll
        for (int o = 0; o < NOUT2; o++) acc[j][o] = 0.f;

#pragma unroll
    for (int t = 0; t < 4; t++) {
        const int k4i = t * 8 + c;
#pragma unroll
        for (int o = 0; o < NOUT2; o++) {
            float4 w = sW[k4i * WPAD + o];
#pragma unroll
            for (int j = 0; j < NPT; j++)
                acc[j][o] += xv[j][t].x * w.x + xv[j][t].y * w.y
                           + xv[j][t].z * w.z + xv[j][t].w * w.w;
        }
    }

    // reduce each (node, o) over the 8-lane group
#pragma unroll
    for (int j = 0; j < NPT; j++)
#pragma unroll
        for (int o = 0; o < NOUT2; o++) {
            acc[j][o] += __shfl_xor_sync(0xFFFFFFFFu, acc[j][o], 4);
            acc[j][o] += __shfl_xor_sync(0xFFFFFFFFu, acc[j][o], 2);
            acc[j][o] += __shfl_xor_sync(0xFFFFFFFFu, acc[j][o], 1);
        }

    if (c == 0) {
#pragma unroll
        for (int j = 0; j < NPT; j++) {
            int node = nbase + j;
            if (node >= N_NODES) break;

            __half2 h01 = __floats2half2_rn(acc[j][0], acc[j][1]);
            __half2 h23 = __floats2half2_rn(acc[j][2], acc[j][3]);
            __half2 h4z = __floats2half2_rn(acc[j][4], 0.f);
            uint4 u;
            u.x = *(unsigned*)&h01;
            u.y = *(unsigned*)&h23;
            u.z = *(unsigned*)&h4z;
            u.w = 0u;
            ((uint4*)(g_ylh + (size_t)node * YL_PADH))[0] = u;

            float4* bp = (float4*)(g_base + (size_t)node * AGG_PAD);
            bp[0] = make_float4(acc[j][5] + sb[0], acc[j][6] + sb[1],
                                acc[j][7] + sb[2], acc[j][8] + sb[3]);
            bp[1] = make_float4(acc[j][9] + sb[4], 0.f, 0.f, 0.f);
        }
    }
}

// ---------------------------------------------------------------------------
// Kernel 2: edge scatter. 4 edges per thread (int4 index loads).
// Per edge: ONE 16B gather + ONE v4.f16x2 RED (8 fp16: y0..y4 + count).
// The gathered row is reused directly as the RED operand; slot 5 gets 1.0h.
// ---------------------------------------------------------------------------
__global__ __launch_bounds__(256) void scatter_kernel(
    const int* __restrict__ src,
    const int* __restrict__ dst)
{
    constexpr int E4 = N_EDGES / 4;  // 400000
    int t = blockIdx.x * blockDim.x + threadIdx.x;
    if (t >= E4) return;

    int4 s4 = ((const int4*)src)[t];
    int4 d4 = ((const int4*)dst)[t];

    int ss[4] = {s4.x, s4.y, s4.z, s4.w};
    int dd[4] = {d4.x, d4.y, d4.z, d4.w};

    uint4 u[4];
#pragma unroll
    for (int k = 0; k < 4; k++) {
        unsigned s = (unsigned)ss[k];
        if (s >= (unsigned)N_NODES) s = 0;  // defensive
        u[k] = ((const uint4*)(g_ylh + (size_t)s * YL_PADH))[0];
    }

#pragma unroll
    for (int k = 0; k < 4; k++) {
        unsigned d = (unsigned)dd[k];
        if (d >= (unsigned)N_NODES) continue;

        // slot5 (high half of .z) <- 1.0h (0x3C00): degree count
        uint4 v = u[k];
        v.z = (v.z & 0x0000FFFFu) | 0x3C000000u;
        red_add_v4_f16x2(g_aggh + (size_t)d * YL_PADH, v);
    }
}

// ---------------------------------------------------------------------------
// Kernel 3: finalize, fully coalesced.
//   out[n][o] = base[n][o] + f32(aggh[n][o]) / max(f32(cnt), 1)
// ---------------------------------------------------------------------------
__global__ __launch_bounds__(256) void finalize_kernel(float* __restrict__ out)
{
    __shared__ float s_out[256 * D_OUT];  // 1280 floats = 320 float4

    int tid  = threadIdx.x;
    int node = blockIdx.x * 256 + tid;

    if (node < N_NODES) {
        uint4 au = ((const uint4*)(g_aggh + (size_t)node * YL_PADH))[0];
        const float4* bp = (const float4*)(g_base + (size_t)node * AGG_PAD);
        float4 b0 = bp[0], b1 = bp[1];

        float2 a01 = __half22float2(*(__half2*)&au.x);
        float2 a23 = __half22float2(*(__half2*)&au.y);
        float2 a4c = __half22float2(*(__half2*)&au.z);

        float inv = 1.0f / fmaxf(a4c.y, 1.0f);   // count in slot 5

        s_out[tid * D_OUT + 0] = b0.x + a01.x * inv;
        s_out[tid * D_OUT + 1] = b0.y + a01.y * inv;
        s_out[tid * D_OUT + 2] = b0.z + a23.x * inv;
        s_out[tid * D_OUT + 3] = b0.w + a23.y * inv;
        s_out[tid * D_OUT + 4] = b1.x + a4c.x * inv;
    }
    __syncthreads();

    int base_f  = blockIdx.x * 256 * D_OUT;
    int total_f = N_NODES * D_OUT;
#pragma unroll
    for (int j = tid; j < 320; j += 256) {
        int f = base_f + j * 4;
        if (f + 3 < total_f) {
            ((float4*)out)[base_f / 4 + j] = ((const float4*)s_out)[j];
        } else if (f < total_f) {
            for (int q = 0; q < total_f - f; q++)
                out[f + q] = s_out[j * 4 + q];
        }
    }
}

// ---------------------------------------------------------------------------
// Launch
// Inputs (metadata order): x [N*128 f32], edge_index [2*E int32 on device],
//                          W_l [5*128 f32], b_l [5 f32], W_r [5*128 f32]
// Output: [N*5 f32]
// ---------------------------------------------------------------------------
extern "C" void kernel_launch(void* const* d_in, const int* in_sizes, int n_in,
                              void* d_out, int out_size)
{
    const float* x    = (const float*)d_in[0];
    const int*   eidx = (const int*)d_in[1];
    const float* Wl   = (const float*)d_in[2];
    const float* bl   = (const float*)d_in[3];
    const float* Wr   = (const float*)d_in[4];
    float*       out  = (float*)d_out;

    const int* src = eidx;            // edge_index[0]
    const int* dst = eidx + N_EDGES;  // edge_index[1]

    {
        int blocks = (N_NODES + NPB2 - 1) / NPB2;   // 782; also zeroes g_aggh
        proj_kernel<<<blocks, 256>>>(x, Wl, bl, Wr);
    }
    {
        constexpr int E4 = N_EDGES / 4;
        scatter_kernel<<<(E4 + 255) / 256, 256>>>(src, dst);
    }
    {
        int blocks = (N_NODES + 255) / 256;
        finalize_kernel<<<blocks, 256>>>(out);
    }
}